// round 1
// baseline (speedup 1.0000x reference)
#include <cuda_runtime.h>

// ============================================================================
// TTConv: fold the entire TT contraction + per-channel conv into ONE dense
// 256->256 3x3 convolution.
//
//   W[o,ic,r]        = sum_{u,v} G1[a,u,r,i] G2[c,v,u,j] G3[d,v,k]
//   Weff[o,ic,dy,dx] = sum_r W[o,ic,r] * conv_w[r,dy,dx]
//   beff[o]          = sum_{ic,r} W[o,ic,r] * conv_b[r]
//   out[b,o,h,w]     = beff[o] + sum_{ic,dy,dx} Weff * X[b,ic,h+dy-1,w+dx-1]
//
// with o = a*64 + c*8 + d, ic = i*64 + j*8 + k   (both row-major, last fastest)
// ============================================================================

// Scratch (allocation-free rule: __device__ globals)
__device__ float g_P[8 * 8 * 8 * 8 * 16];   // [c][d][j][k][u]   256 KB
__device__ float g_W[256 * 256 * 16];       // [o][ic][r]        4 MB
__device__ float g_Weff[256 * 256 * 9];     // [o][ic][tap]      2.25 MB
__device__ float g_beff[256];

// ---------------------------------------------------------------------------
// Precompute step 1: P[c,d,j,k,u] = sum_v G2[c,v,u,j] * G3[d,v,k]
//   core2: (8*16, 16*8) row-major -> G2[c,v,u,j] = core2[(c*16+v)*128 + u*8+j]
//   core3: (8*1, 16*8)  row-major -> G3[d,v,k]   = core3[d*128 + v*8 + k]
// ---------------------------------------------------------------------------
__global__ void precompute_P(const float* __restrict__ core2,
                             const float* __restrict__ core3) {
    int idx = blockIdx.x * blockDim.x + threadIdx.x;  // 65536
    int u = idx & 15;
    int k = (idx >> 4) & 7;
    int j = (idx >> 7) & 7;
    int d = (idx >> 10) & 7;
    int c = idx >> 13;
    float s = 0.f;
#pragma unroll
    for (int v = 0; v < 16; ++v)
        s += core2[(c * 16 + v) * 128 + u * 8 + j] * core3[d * 128 + v * 8 + k];
    g_P[idx] = s;
}

// ---------------------------------------------------------------------------
// Precompute step 2: W[o,ic,r] = sum_u G1[a,u,r,i] * P[c,d,j,k,u]
//   core1: (4*16, 16*4) row-major -> G1[a,u,r,i] = core1[(a*16+u)*64 + r*4+i]
// ---------------------------------------------------------------------------
__global__ void precompute_W(const float* __restrict__ core1) {
    int idx = blockIdx.x * blockDim.x + threadIdx.x;  // 1048576
    int r  = idx & 15;
    int ic = (idx >> 4) & 255;
    int o  = idx >> 12;
    int a = o >> 6, c = (o >> 3) & 7, d = o & 7;
    int i = ic >> 6, j = (ic >> 3) & 7, k = ic & 7;
    const float* Pp = &g_P[(((c * 8 + d) * 8 + j) * 8 + k) * 16];
    float s = 0.f;
#pragma unroll
    for (int u = 0; u < 16; ++u)
        s += core1[(a * 16 + u) * 64 + r * 4 + i] * Pp[u];
    g_W[idx] = s;
}

// ---------------------------------------------------------------------------
// Precompute step 3: Weff[o,ic,tap] and beff[o]
//   One block per o (256 threads = one per ic). Deterministic tree reduce.
// ---------------------------------------------------------------------------
__global__ void precompute_Weff(const float* __restrict__ conv_w,
                                const float* __restrict__ conv_b) {
    int o  = blockIdx.x;
    int ic = threadIdx.x;
    float wr[16];
    const float* Wp = &g_W[(o * 256 + ic) * 16];
#pragma unroll
    for (int r = 0; r < 16; ++r) wr[r] = Wp[r];
#pragma unroll
    for (int t = 0; t < 9; ++t) {
        float s = 0.f;
#pragma unroll
        for (int r = 0; r < 16; ++r) s += wr[r] * conv_w[r * 9 + t];
        g_Weff[(o * 256 + ic) * 9 + t] = s;
    }
    float bp = 0.f;
#pragma unroll
    for (int r = 0; r < 16; ++r) bp += wr[r] * conv_b[r];
    __shared__ float red[256];
    red[ic] = bp;
    __syncthreads();
    for (int s = 128; s > 0; s >>= 1) {
        if (ic < s) red[ic] += red[ic + s];
        __syncthreads();
    }
    if (ic == 0) g_beff[o] = red[0];
}

// ---------------------------------------------------------------------------
// Main conv: block = 64 oc x (4 rows x 64 cols), 256 threads.
// Thread = 8 oc x (2 rows x 4 cols) = 64 fp32 accumulators.
// warp (tid/32) -> oc group of 8 (broadcast smem W reads within warp)
// lane -> spatial: gy=lane/16 (2-row group), gx=lane%16 (4-col group)
// ic loop in chunks of 8, X tile + W tile staged through shared.
// ---------------------------------------------------------------------------
__global__ __launch_bounds__(256, 2)
void conv_main(const float* __restrict__ X, float* __restrict__ out) {
    const int ocb = blockIdx.x * 64;
    const int h0  = blockIdx.y * 4;
    const int b   = blockIdx.z;
    const int tid  = threadIdx.x;
    const int warp = tid >> 5;
    const int lane = tid & 31;
    const int gy = lane >> 4;   // 0..1 -> output rows h0 + 2*gy + {0,1}
    const int gx = lane & 15;   // output cols 4*gx + {0..3}

    __shared__ float Xs[8][6][68];     // [ic][row(-1..+4)][col(-1..+64)] 13.1 KB
    __shared__ float Ws[64][8][9];     // [oc_l][ic_l][tap]               18.4 KB

    float acc[8][8];
#pragma unroll
    for (int a = 0; a < 8; ++a)
#pragma unroll
        for (int p = 0; p < 8; ++p) acc[a][p] = 0.f;

    const float* Xb = X + (size_t)b * 256 * 64 * 64;

    for (int icb = 0; icb < 256; icb += 8) {
        __syncthreads();
        // Stage X tile: 8 ic x 6 rows x 66 cols (zero-pad borders)
        for (int e = tid; e < 8 * 6 * 66; e += 256) {
            int ic  = e / 396;
            int rem = e - ic * 396;
            int row = rem / 66;
            int col = rem - row * 66;
            int gr = h0 - 1 + row;
            int gc = col - 1;
            float v = 0.f;
            if (gr >= 0 && gr < 64 && gc >= 0 && gc < 64)
                v = Xb[((icb + ic) * 64 + gr) * 64 + gc];
            Xs[ic][row][col] = v;
        }
        // Stage W tile: 64 oc x (8 ic x 9 taps) = 64 x 72 contiguous floats
        {
            const float* Wg = g_Weff + (size_t)ocb * 2304 + icb * 9;
            float* Wsf = &Ws[0][0][0];
            for (int e = tid; e < 64 * 72; e += 256) {
                int ol = e / 72;
                int rr = e - ol * 72;
                Wsf[ol * 72 + rr] = Wg[(size_t)ol * 2304 + rr];
            }
        }
        __syncthreads();

#pragma unroll 1
        for (int icl = 0; icl < 8; ++icl) {
            // Per-thread X patch: 4 rows x 6 cols
            float xr[4][6];
#pragma unroll
            for (int ry = 0; ry < 4; ++ry)
#pragma unroll
                for (int cx = 0; cx < 6; ++cx)
                    xr[ry][cx] = Xs[icl][2 * gy + ry][4 * gx + cx];

#pragma unroll
            for (int og = 0; og < 8; ++og) {
                float w[9];
#pragma unroll
                for (int t = 0; t < 9; ++t)
                    w[t] = Ws[(warp << 3) + og][icl][t];
#pragma unroll
                for (int ry = 0; ry < 2; ++ry)
#pragma unroll
                    for (int cx = 0; cx < 4; ++cx) {
                        float s = acc[og][ry * 4 + cx];
#pragma unroll
                        for (int dy = 0; dy < 3; ++dy)
#pragma unroll
                            for (int dx = 0; dx < 3; ++dx)
                                s += w[dy * 3 + dx] * xr[ry + dy][cx + dx];
                        acc[og][ry * 4 + cx] = s;
                    }
            }
        }
    }

    // Epilogue: bias + vectorized stores (float4 per row segment)
#pragma unroll
    for (int og = 0; og < 8; ++og) {
        int oc = ocb + (warp << 3) + og;
        float bv = g_beff[oc];
#pragma unroll
        for (int ry = 0; ry < 2; ++ry) {
            int h = h0 + 2 * gy + ry;
            float4 v;
            v.x = acc[og][ry * 4 + 0] + bv;
            v.y = acc[og][ry * 4 + 1] + bv;
            v.z = acc[og][ry * 4 + 2] + bv;
            v.w = acc[og][ry * 4 + 3] + bv;
            float* op = out + (((size_t)b * 256 + oc) * 64 + h) * 64 + 4 * gx;
            *reinterpret_cast<float4*>(op) = v;
        }
    }
}

// ---------------------------------------------------------------------------
extern "C" void kernel_launch(void* const* d_in, const int* in_sizes, int n_in,
                              void* d_out, int out_size) {
    // Identify inputs robustly by element count (all distinct):
    //   X=8388608, conv_w=144, conv_b=16, core1=4096, core2=16384, core3=1024
    const float *X = 0, *cw = 0, *cb = 0, *c1 = 0, *c2 = 0, *c3 = 0;
    for (int i = 0; i < n_in; ++i) {
        const float* p = (const float*)d_in[i];
        switch (in_sizes[i]) {
            case 8388608: X  = p; break;
            case 144:     cw = p; break;
            case 16:      cb = p; break;
            case 4096:    c1 = p; break;
            case 16384:   c2 = p; break;
            case 1024:    c3 = p; break;
            default: break;
        }
    }
    precompute_P<<<256, 256>>>(c2, c3);
    precompute_W<<<4096, 256>>>(c1);
    precompute_Weff<<<256, 256>>>(cw, cb);

    dim3 grid(4, 16, 8);  // oc tiles, h tiles, batch
    conv_main<<<grid, 256>>>(X, (float*)d_out);
}

// round 3
// speedup vs baseline: 6.0067x; 6.0067x over previous
#include <cuda_runtime.h>
#include <cuda_fp16.h>
#include <cstdint>

// ============================================================================
// TTConv folded into ONE dense 256->256 3x3 conv, executed as fp16 mma.sync
// implicit GEMM (baseline PTX only: mma.sync / ldmatrix / cp.async — the
// harness targets compute_103, which rejects sm_103a-only tcgen05 PTX).
//
//   W[o,ic,r]        = sum_{u,v} G1 G2 G3          (TT cores collapsed)
//   Weff[o,ic,tap]   = sum_r W[o,ic,r] * conv_w[r,tap]
//   beff[o]          = sum_{ic,r} W[o,ic,r] * conv_b[r]
//   out[b,o,h,w]     = beff[o] + sum_{ic,tap} Weff * Xpad[b,h+dy,w+dx,ic]
// ============================================================================

// ---------------- device scratch (no allocations allowed) -------------------
__device__ float  g_P[8 * 8 * 8 * 8 * 16];
__device__ float  g_W[256 * 256 * 16];
__device__ __half g_Wh[72 * 256 * 32];              // A chunks [icb*9+tap][o][32]
__device__ float  g_beff[256];
__device__ __half g_Xh[8ull * 66 * 66 * 256];       // padded NHWC fp16

// ---------------- helpers ---------------------------------------------------
__device__ __forceinline__ uint32_t smem_u32(const void* p) {
    uint32_t a;
    asm("{ .reg .u64 t; cvta.to.shared.u64 t, %1; cvt.u32.u64 %0, t; }"
        : "=r"(a) : "l"(p));
    return a;
}

#define CP16(dst, src) \
    asm volatile("cp.async.ca.shared.global [%0], [%1], 16;" \
                 :: "r"(dst), "l"(src) : "memory")
#define CP_COMMIT() asm volatile("cp.async.commit_group;" ::: "memory")
#define CP_WAIT1()  asm volatile("cp.async.wait_group 1;" ::: "memory")
#define CP_WAIT0()  asm volatile("cp.async.wait_group 0;" ::: "memory")

#define LDSM4(r0, r1, r2, r3, addr) \
    asm volatile("ldmatrix.sync.aligned.m8n8.x4.shared.b16 {%0,%1,%2,%3}, [%4];" \
                 : "=r"(r0), "=r"(r1), "=r"(r2), "=r"(r3) : "r"(addr))

#define MMA16816(c, a0, a1, a2, a3, b0, b1) \
    asm volatile("mma.sync.aligned.m16n8k16.row.col.f32.f16.f16.f32 " \
                 "{%0,%1,%2,%3}, {%4,%5,%6,%7}, {%8,%9}, {%0,%1,%2,%3};" \
                 : "+f"((c)[0]), "+f"((c)[1]), "+f"((c)[2]), "+f"((c)[3]) \
                 : "r"(a0), "r"(a1), "r"(a2), "r"(a3), "r"(b0), "r"(b1))

// ---------------------------------------------------------------------------
// Precompute 1: P[c,d,j,k,u] = sum_v G2[c,v,u,j] * G3[d,v,k]
// ---------------------------------------------------------------------------
__global__ void precompute_P(const float* __restrict__ core2,
                             const float* __restrict__ core3) {
    int idx = blockIdx.x * blockDim.x + threadIdx.x;
    int u = idx & 15, k = (idx >> 4) & 7, j = (idx >> 7) & 7;
    int d = (idx >> 10) & 7, c = idx >> 13;
    float s = 0.f;
#pragma unroll
    for (int v = 0; v < 16; ++v)
        s += core2[(c * 16 + v) * 128 + u * 8 + j] * core3[d * 128 + v * 8 + k];
    g_P[idx] = s;
}

// ---------------------------------------------------------------------------
// Precompute 2: W[o,ic,r] = sum_u G1[a,u,r,i] * P[c,d,j,k,u]
// ---------------------------------------------------------------------------
__global__ void precompute_W(const float* __restrict__ core1) {
    int idx = blockIdx.x * blockDim.x + threadIdx.x;
    int r = idx & 15, ic = (idx >> 4) & 255, o = idx >> 12;
    int a = o >> 6, c = (o >> 3) & 7, d = o & 7;
    int i = ic >> 6, j = (ic >> 3) & 7, k = ic & 7;
    const float* Pp = &g_P[(((c * 8 + d) * 8 + j) * 8 + k) * 16];
    float s = 0.f;
#pragma unroll
    for (int u = 0; u < 16; ++u)
        s += core1[(a * 16 + u) * 64 + r * 4 + i] * Pp[u];
    g_W[idx] = s;
}

// ---------------------------------------------------------------------------
// Precompute 3: fold conv taps -> fp16 A chunks [icb*9+tap][o][32] + bias
// ---------------------------------------------------------------------------
__global__ void precompute_Weff(const float* __restrict__ conv_w,
                                const float* __restrict__ conv_b) {
    int o = blockIdx.x, ic = threadIdx.x;
    float wr[16];
    const float* Wp = &g_W[(o * 256 + ic) * 16];
#pragma unroll
    for (int r = 0; r < 16; ++r) wr[r] = Wp[r];
    int kk = ic & 31, icb = ic >> 5;
#pragma unroll
    for (int tap = 0; tap < 9; ++tap) {
        float s = 0.f;
#pragma unroll
        for (int r = 0; r < 16; ++r) s += wr[r] * conv_w[r * 9 + tap];
        g_Wh[((size_t)(icb * 9 + tap) * 256 + o) * 32 + kk] = __float2half_rn(s);
    }
    float bp = 0.f;
#pragma unroll
    for (int r = 0; r < 16; ++r) bp += wr[r] * conv_b[r];
    __shared__ float red[256];
    red[ic] = bp;
    __syncthreads();
    for (int s = 128; s > 0; s >>= 1) {
        if (ic < s) red[ic] += red[ic + s];
        __syncthreads();
    }
    if (ic == 0) g_beff[o] = red[0];
}

// ---------------------------------------------------------------------------
// Precompute 4a: zero padded NHWC buffer (borders must be 0)
//   total halves = 8*66*66*256 -> uint4 count = 66*66*256 = 1,115,136
// ---------------------------------------------------------------------------
__global__ void zero_xpad() {
    size_t i = (size_t)blockIdx.x * 256 + threadIdx.x;
    reinterpret_cast<uint4*>(g_Xh)[i] = make_uint4(0, 0, 0, 0);
}

// ---------------------------------------------------------------------------
// Precompute 4b: NCHW fp32 -> padded NHWC fp16
// ---------------------------------------------------------------------------
__global__ void build_xpad(const float* __restrict__ X) {
    int y = blockIdx.x, icb = blockIdx.y, b = blockIdx.z;
    int tid = threadIdx.x;
    __shared__ float s[32 * 65];
    for (int i = tid; i < 2048; i += 256) {
        int icl = i >> 6, x = i & 63;
        s[icl * 65 + x] = X[(((size_t)b * 256 + icb * 32 + icl) * 64 + y) * 64 + x];
    }
    __syncthreads();
    for (int i = tid; i < 1024; i += 256) {
        int x = i >> 4, pr = i & 15;
        __half2 h = __floats2half2_rn(s[(2 * pr) * 65 + x], s[(2 * pr + 1) * 65 + x]);
        *reinterpret_cast<__half2*>(
            g_Xh + (((size_t)b * 66 + y + 1) * 66 + (x + 1)) * 256 + icb * 32 + 2 * pr) = h;
    }
}

// ---------------------------------------------------------------------------
// Main kernel: fp16 mma.sync implicit GEMM.
//   CTA: 128 o x 256 pixels (4 rows x 64 cols). 512 thr = 4(M) x 4(N) warps.
//   K: 72 chunks of 32 (icb 0..7, tap 0..8). cp.async 2-deep pipeline.
// Smem: A 2 x 128 rows x 80B = 20480 ; Xs 2 x (6*66 rows x 80B) = 63360
// ---------------------------------------------------------------------------
static constexpr int A_BUF  = 10240;     // bytes per A buffer (128 x 80)
static constexpr int XS_BUF = 31680;     // bytes per Xs buffer (396 x 80)
static constexpr int XS_OFF = 2 * A_BUF; // 20480
static constexpr int SMEM_DYN = XS_OFF + 2 * XS_BUF;  // 83840

__global__ __launch_bounds__(512, 1)
void conv_mma(float* __restrict__ out) {
    extern __shared__ char smc[];
    const uint32_t sb = smem_u32(smc);
    const int tid  = threadIdx.x;
    const int warp = tid >> 5, lane = tid & 31;
    const int warpM = warp >> 2;         // 0..3 -> o block of 32
    const int warpR = warp & 3;          // 0..3 -> output row within tile
    const int h0 = blockIdx.x * 4;
    const int b  = blockIdx.y;
    const int Mbase = blockIdx.z * 128;

    // lane-invariant parts of ldmatrix addresses
    const uint32_t aLane = (uint32_t)((warpM * 32 + (lane & 15)) * 80 + (lane >> 4) * 16);
    const uint32_t xLane = (uint32_t)((((lane >> 4) & 1) * 8 + (lane & 7)) * 80 +
                                      ((lane >> 3) & 1) * 16);

    // ---- staging lambdas -------------------------------------------------
    auto stageA = [&](int t, int buf) {
        const char* src = (const char*)(g_Wh + (size_t)t * 256 * 32 + (size_t)Mbase * 32);
        uint32_t dst = sb + buf * A_BUF;
        int o = tid >> 2, c = tid & 3;
        CP16(dst + o * 80 + c * 16, src + o * 64 + c * 16);
    };
    auto stageXs = [&](int icb, int buf) {
        uint32_t dst = sb + XS_OFF + buf * XS_BUF;
        const char* base = (const char*)g_Xh;
        for (int e = tid; e < 1584; e += 512) {
            int pix = e >> 2, c = e & 3;
            int yy = pix / 66, cc = pix - yy * 66;
            const char* src = base +
                ((((size_t)b * 66 + h0 + yy) * 66 + cc) * 256 + icb * 32) * 2 + c * 16;
            CP16(dst + pix * 80 + c * 16, src);
        }
    };

    float acc[2][8][4];
#pragma unroll
    for (int m = 0; m < 2; ++m)
#pragma unroll
        for (int n = 0; n < 8; ++n)
#pragma unroll
            for (int q = 0; q < 4; ++q) acc[m][n][q] = 0.f;

    // ---- pipeline prologue ----
    stageXs(0, 0);
    stageA(0, 0);
    CP_COMMIT();
    stageA(1, 1);
    CP_COMMIT();

    int tap = 0, icb = 0;
    for (int t = 0; t < 72; ++t) {
        if (t < 71) CP_WAIT1(); else CP_WAIT0();
        __syncthreads();

        const int dy = tap / 3, dx = tap - dy * 3;
        const uint32_t aAddr = sb + (t & 1) * A_BUF + aLane;
        const uint32_t xAddr = sb + XS_OFF + (icb & 1) * XS_BUF +
                               (uint32_t)(((warpR + dy) * 66 + dx) * 80) + xLane;

#pragma unroll
        for (int ks = 0; ks < 2; ++ks) {
            uint32_t a0, a1, a2, a3, e0, e1, e2, e3;
            LDSM4(a0, a1, a2, a3, aAddr + ks * 32);
            LDSM4(e0, e1, e2, e3, aAddr + 16 * 80 + ks * 32);
#pragma unroll
            for (int p = 0; p < 4; ++p) {
                uint32_t b0, b1, b2, b3;
                LDSM4(b0, b1, b2, b3, xAddr + p * (16 * 80) + ks * 32);
                MMA16816(acc[0][2 * p],     a0, a1, a2, a3, b0, b1);
                MMA16816(acc[0][2 * p + 1], a0, a1, a2, a3, b2, b3);
                MMA16816(acc[1][2 * p],     e0, e1, e2, e3, b0, b1);
                MMA16816(acc[1][2 * p + 1], e0, e1, e2, e3, b2, b3);
            }
        }
        __syncthreads();

        int s = t + 2;
        if (s < 72) {
            if (s % 9 == 0) stageXs(s / 9, (s / 9) & 1);
            stageA(s, s & 1);
            CP_COMMIT();
        }
        if (++tap == 9) { tap = 0; ++icb; }
    }

    // ---- epilogue: bias + direct float2 stores ----
    const int h = h0 + warpR;
#pragma unroll
    for (int mt = 0; mt < 2; ++mt) {
        int oLo = Mbase + warpM * 32 + mt * 16 + (lane >> 2);
        float bvLo = g_beff[oLo];
        float bvHi = g_beff[oLo + 8];
        float* rowLo = out + (((size_t)b * 256 + oLo) * 64 + h) * 64;
        float* rowHi = rowLo + (size_t)8 * 64 * 64;
#pragma unroll
        for (int nt = 0; nt < 8; ++nt) {
            int w = nt * 8 + (lane & 3) * 2;
            float2 vLo = make_float2(acc[mt][nt][0] + bvLo, acc[mt][nt][1] + bvLo);
            float2 vHi = make_float2(acc[mt][nt][2] + bvHi, acc[mt][nt][3] + bvHi);
            *reinterpret_cast<float2*>(rowLo + w) = vLo;
            *reinterpret_cast<float2*>(rowHi + w) = vHi;
        }
    }
}

// ---------------------------------------------------------------------------
extern "C" void kernel_launch(void* const* d_in, const int* in_sizes, int n_in,
                              void* d_out, int out_size) {
    const float *X = 0, *cw = 0, *cb = 0, *c1 = 0, *c2 = 0, *c3 = 0;
    for (int i = 0; i < n_in; ++i) {
        const float* p = (const float*)d_in[i];
        switch (in_sizes[i]) {
            case 8388608: X  = p; break;
            case 144:     cw = p; break;
            case 16:      cb = p; break;
            case 4096:    c1 = p; break;
            case 16384:   c2 = p; break;
            case 1024:    c3 = p; break;
            default: break;
        }
    }

    cudaFuncSetAttribute(conv_mma, cudaFuncAttributeMaxDynamicSharedMemorySize,
                         SMEM_DYN);

    precompute_P<<<256, 256>>>(c2, c3);
    precompute_W<<<4096, 256>>>(c1);
    precompute_Weff<<<256, 256>>>(cw, cb);
    zero_xpad<<<4356, 256>>>();
    build_xpad<<<dim3(64, 8, 8), 256>>>(X);

    conv_mma<<<dim3(16, 8, 2), 512, SMEM_DYN>>>((float*)d_out);
}

// round 4
// speedup vs baseline: 7.3463x; 1.2230x over previous
#include <cuda_runtime.h>
#include <cuda_fp16.h>
#include <cstdint>

// ============================================================================
// TTConv folded into ONE dense 256->256 3x3 conv, executed as fp16 mma.sync
// implicit GEMM. Pipeline restructured to ic-block granularity:
//   - A for all 9 taps of an ic-block staged at once (swizzled, linear copy)
//   - 2 __syncthreads per ic-block (16 total) instead of 144
//   - cp.async staging overlaps a full ic-block of compute
// ============================================================================

// ---------------- device scratch (no allocations allowed) -------------------
__device__ float  g_P[8 * 8 * 8 * 8 * 16];
__device__ float  g_W[256 * 256 * 16];
// A, pre-swizzled: [Mhalf 2][icb 8][tap 9][o_local 128][k 32(swizzled)]
__device__ __half g_Wsw[2 * 8 * 9 * 128 * 32];
__device__ float  g_beff[256];
__device__ __half g_Xh[8ull * 66 * 66 * 256];       // padded NHWC fp16

// ---------------- helpers ---------------------------------------------------
__device__ __forceinline__ uint32_t smem_u32(const void* p) {
    uint32_t a;
    asm("{ .reg .u64 t; cvta.to.shared.u64 t, %1; cvt.u32.u64 %0, t; }"
        : "=r"(a) : "l"(p));
    return a;
}

#define CP16(dst, src) \
    asm volatile("cp.async.ca.shared.global [%0], [%1], 16;" \
                 :: "r"(dst), "l"(src) : "memory")
#define CP_COMMIT() asm volatile("cp.async.commit_group;" ::: "memory")
#define CP_WAIT1()  asm volatile("cp.async.wait_group 1;" ::: "memory")
#define CP_WAIT0()  asm volatile("cp.async.wait_group 0;" ::: "memory")

#define LDSM4(r0, r1, r2, r3, addr) \
    asm volatile("ldmatrix.sync.aligned.m8n8.x4.shared.b16 {%0,%1,%2,%3}, [%4];" \
                 : "=r"(r0), "=r"(r1), "=r"(r2), "=r"(r3) : "r"(addr))

#define MMA16816(c, a0, a1, a2, a3, b0, b1) \
    asm volatile("mma.sync.aligned.m16n8k16.row.col.f32.f16.f16.f32 " \
                 "{%0,%1,%2,%3}, {%4,%5,%6,%7}, {%8,%9}, {%0,%1,%2,%3};" \
                 : "+f"((c)[0]), "+f"((c)[1]), "+f"((c)[2]), "+f"((c)[3]) \
                 : "r"(a0), "r"(a1), "r"(a2), "r"(a3), "r"(b0), "r"(b1))

// ---------------------------------------------------------------------------
// Precompute 1: P[c,d,j,k,u] = sum_v G2[c,v,u,j] * G3[d,v,k]
// ---------------------------------------------------------------------------
__global__ void precompute_P(const float* __restrict__ core2,
                             const float* __restrict__ core3) {
    int idx = blockIdx.x * blockDim.x + threadIdx.x;
    int u = idx & 15, k = (idx >> 4) & 7, j = (idx >> 7) & 7;
    int d = (idx >> 10) & 7, c = idx >> 13;
    float s = 0.f;
#pragma unroll
    for (int v = 0; v < 16; ++v)
        s += core2[(c * 16 + v) * 128 + u * 8 + j] * core3[d * 128 + v * 8 + k];
    g_P[idx] = s;
}

// ---------------------------------------------------------------------------
// Precompute 2: W[o,ic,r] = sum_u G1[a,u,r,i] * P[c,d,j,k,u]
// ---------------------------------------------------------------------------
__global__ void precompute_W(const float* __restrict__ core1) {
    int idx = blockIdx.x * blockDim.x + threadIdx.x;
    int r = idx & 15, ic = (idx >> 4) & 255, o = idx >> 12;
    int a = o >> 6, c = (o >> 3) & 7, d = o & 7;
    int i = ic >> 6, j = (ic >> 3) & 7, k = ic & 7;
    const float* Pp = &g_P[(((c * 8 + d) * 8 + j) * 8 + k) * 16];
    float s = 0.f;
#pragma unroll
    for (int u = 0; u < 16; ++u)
        s += core1[(a * 16 + u) * 64 + r * 4 + i] * Pp[u];
    g_W[idx] = s;
}

// ---------------------------------------------------------------------------
// Precompute 3: fold conv taps -> fp16 A in final swizzled smem layout + bias
//   smem A rows are 64B (32 halves); swizzle: phys 16B-chunk = c16 ^ ((o&127)>>1 & 3)
// ---------------------------------------------------------------------------
__global__ void precompute_Weff(const float* __restrict__ conv_w,
                                const float* __restrict__ conv_b) {
    int o = blockIdx.x, ic = threadIdx.x;
    float wr[16];
    const float* Wp = &g_W[(o * 256 + ic) * 16];
#pragma unroll
    for (int r = 0; r < 16; ++r) wr[r] = Wp[r];
    int kk = ic & 31, icb = ic >> 5;
    int o_l = o & 127, mh = o >> 7;
    int swkk = ((((kk >> 3) ^ ((o_l >> 1) & 3)) << 3) | (kk & 7));
#pragma unroll
    for (int tap = 0; tap < 9; ++tap) {
        float s = 0.f;
#pragma unroll
        for (int r = 0; r < 16; ++r) s += wr[r] * conv_w[r * 9 + tap];
        g_Wsw[((((size_t)mh * 8 + icb) * 9 + tap) * 128 + o_l) * 32 + swkk] =
            __float2half_rn(s);
    }
    float bp = 0.f;
#pragma unroll
    for (int r = 0; r < 16; ++r) bp += wr[r] * conv_b[r];
    __shared__ float red[256];
    red[ic] = bp;
    __syncthreads();
    for (int s = 128; s > 0; s >>= 1) {
        if (ic < s) red[ic] += red[ic + s];
        __syncthreads();
    }
    if (ic == 0) g_beff[o] = red[0];
}

// ---------------------------------------------------------------------------
// Precompute 4a: zero ONLY the border pixels of the padded NHWC buffer
//   260 border pixels/image x 8 images x 32 uint4 = 66560 uint4
// ---------------------------------------------------------------------------
__global__ void zero_borders() {
    int idx = blockIdx.x * 256 + threadIdx.x;
    if (idx >= 66560) return;
    int q = idx & 31;
    int pb = idx >> 5;
    int b = pb / 260, p = pb - b * 260;
    int y, x;
    if (p < 66)        { y = 0;       x = p; }
    else if (p < 132)  { y = 65;      x = p - 66; }
    else if (p < 196)  { y = p - 131; x = 0; }
    else               { y = p - 195; x = 65; }
    reinterpret_cast<uint4*>(g_Xh + (((size_t)b * 66 + y) * 66 + x) * 256)[q] =
        make_uint4(0, 0, 0, 0);
}

// ---------------------------------------------------------------------------
// Precompute 4b: NCHW fp32 -> padded NHWC fp16 (interior)
// ---------------------------------------------------------------------------
__global__ void build_xpad(const float* __restrict__ X) {
    int y = blockIdx.x, icb = blockIdx.y, b = blockIdx.z;
    int tid = threadIdx.x;
    __shared__ float s[32 * 65];
    for (int i = tid; i < 2048; i += 256) {
        int icl = i >> 6, x = i & 63;
        s[icl * 65 + x] = X[(((size_t)b * 256 + icb * 32 + icl) * 64 + y) * 64 + x];
    }
    __syncthreads();
    for (int i = tid; i < 1024; i += 256) {
        int x = i >> 4, pr = i & 15;
        __half2 h = __floats2half2_rn(s[(2 * pr) * 65 + x], s[(2 * pr + 1) * 65 + x]);
        *reinterpret_cast<__half2*>(
            g_Xh + (((size_t)b * 66 + y + 1) * 66 + (x + 1)) * 256 + icb * 32 + 2 * pr) = h;
    }
}

// ---------------------------------------------------------------------------
// Main kernel. CTA: 128 o x 256 pixels (4 rows x 64 cols). 512 thr.
// Pipeline over 8 ic-blocks; per ic-block: 9 taps x 32 k, 288 MMAs/warp.
// Smem: A 2 x 73728 (swizzled 64B rows) + Xs 2 x 31680 (80B padded rows)
// ---------------------------------------------------------------------------
static constexpr int A_CH   = 8192;            // per tap chunk: 128 x 64B
static constexpr int A_BUF  = 9 * A_CH;        // 73728
static constexpr int XS_BUF = 31680;           // 396 rows x 80B
static constexpr int XS_OFF = 2 * A_BUF;       // 147456
static constexpr int SMEM_DYN = XS_OFF + 2 * XS_BUF;  // 210816

__global__ __launch_bounds__(512, 1)
void conv_mma(float* __restrict__ out) {
    extern __shared__ char smc[];
    const uint32_t sb = smem_u32(smc);
    const int tid  = threadIdx.x;
    const int warp = tid >> 5, lane = tid & 31;
    const int warpM = warp >> 2;         // 0..3 -> o block of 32
    const int warpR = warp & 3;          // 0..3 -> output row within tile
    const int h0 = blockIdx.x * 4;
    const int b  = blockIdx.y;
    const int Mbase = blockIdx.z * 128;
    const int mh = blockIdx.z;

    // A ldmatrix addressing (swizzled 64B rows):
    //   row = warpM*32 + (lane&15) [+16 for mt=1]; hi = lane>>4
    //   chunk(ks) = ks*2 + hi; phys = chunk ^ ((row>>1)&3)
    const int rowA = warpM * 32 + (lane & 15);
    const int hi   = lane >> 4;
    const int swA  = ((lane & 15) >> 1) & 3;
    const uint32_t aLane0 = (uint32_t)(rowA * 64 + ((hi ^ swA) << 4));        // ks=0
    // ks=1 chunk = phys0 ^ 2 -> +/- 32 bytes; precompute both
    const uint32_t aLane1 = (uint32_t)(rowA * 64 + (((2 + hi) ^ swA) << 4));
    // mt=1: row += 16 -> +16*64 bytes, same swizzle
    const uint32_t xLane = (uint32_t)((((lane >> 4) & 1) * 8 + (lane & 7)) * 80 +
                                      ((lane >> 3) & 1) * 16);

    // ---- staging ----------------------------------------------------------
    auto stageA = [&](int icb, int buf) {
        const char* src = (const char*)(g_Wsw + (((size_t)mh * 8 + icb) * 9) * 128 * 32);
        uint32_t dst = sb + buf * A_BUF;
#pragma unroll
        for (int i = 0; i < 9; ++i) {
            int e = tid + i * 512;                 // 4608 x 16B
            CP16(dst + e * 16, src + e * 16);
        }
    };
    auto stageXs = [&](int icb, int buf) {
        uint32_t dst = sb + XS_OFF + buf * XS_BUF;
        const char* base = (const char*)g_Xh;
        for (int e = tid; e < 1584; e += 512) {
            int pix = e >> 2, c = e & 3;
            int yy = pix / 66, cc = pix - yy * 66;
            const char* src = base +
                ((((size_t)b * 66 + h0 + yy) * 66 + cc) * 256 + icb * 32) * 2 + c * 16;
            CP16(dst + pix * 80 + c * 16, src);
        }
    };

    float acc[2][8][4];
#pragma unroll
    for (int m = 0; m < 2; ++m)
#pragma unroll
        for (int n = 0; n < 8; ++n)
#pragma unroll
            for (int q = 0; q < 4; ++q) acc[m][n][q] = 0.f;

    // ---- prologue: stage icb 0 and 1 ----
    stageXs(0, 0); stageA(0, 0); CP_COMMIT();
    stageXs(1, 1); stageA(1, 1); CP_COMMIT();

    for (int icb = 0; icb < 8; ++icb) {
        const int buf = icb & 1;
        if (icb < 7) CP_WAIT1(); else CP_WAIT0();
        __syncthreads();                          // staged data visible

        const uint32_t aBase = sb + buf * A_BUF;
        const uint32_t xBase = sb + XS_OFF + buf * XS_BUF;

#pragma unroll
        for (int tap = 0; tap < 9; ++tap) {
            const int dy = tap / 3, dx = tap - dy * 3;
            const uint32_t aT = aBase + tap * A_CH;
            const uint32_t xT = xBase + (uint32_t)(((warpR + dy) * 66 + dx) * 80) + xLane;

#pragma unroll
            for (int ks = 0; ks < 2; ++ks) {
                const uint32_t aAddr = aT + (ks ? aLane1 : aLane0);
                uint32_t a0, a1, a2, a3, e0, e1, e2, e3;
                LDSM4(a0, a1, a2, a3, aAddr);
                LDSM4(e0, e1, e2, e3, aAddr + 16 * 64);
#pragma unroll
                for (int p = 0; p < 4; ++p) {
                    uint32_t b0, b1, b2, b3;
                    LDSM4(b0, b1, b2, b3, xT + p * (16 * 80) + ks * 32);
                    MMA16816(acc[0][2 * p],     a0, a1, a2, a3, b0, b1);
                    MMA16816(acc[0][2 * p + 1], a0, a1, a2, a3, b2, b3);
                    MMA16816(acc[1][2 * p],     e0, e1, e2, e3, b0, b1);
                    MMA16816(acc[1][2 * p + 1], e0, e1, e2, e3, b2, b3);
                }
            }
        }
        __syncthreads();                          // buffer free for re-staging
        if (icb + 2 < 8) {
            stageXs(icb + 2, buf);
            stageA(icb + 2, buf);
            CP_COMMIT();
        }
    }

    // ---- epilogue: bias + direct float2 stores ----
    const int h = h0 + warpR;
#pragma unroll
    for (int mt = 0; mt < 2; ++mt) {
        int oLo = Mbase + warpM * 32 + mt * 16 + (lane >> 2);
        float bvLo = g_beff[oLo];
        float bvHi = g_beff[oLo + 8];
        float* rowLo = out + (((size_t)b * 256 + oLo) * 64 + h) * 64;
        float* rowHi = rowLo + (size_t)8 * 64 * 64;
#pragma unroll
        for (int nt = 0; nt < 8; ++nt) {
            int w = nt * 8 + (lane & 3) * 2;
            float2 vLo = make_float2(acc[mt][nt][0] + bvLo, acc[mt][nt][1] + bvLo);
            float2 vHi = make_float2(acc[mt][nt][2] + bvHi, acc[mt][nt][3] + bvHi);
            *reinterpret_cast<float2*>(rowLo + w) = vLo;
            *reinterpret_cast<float2*>(rowHi + w) = vHi;
        }
    }
}

// ---------------------------------------------------------------------------
extern "C" void kernel_launch(void* const* d_in, const int* in_sizes, int n_in,
                              void* d_out, int out_size) {
    const float *X = 0, *cw = 0, *cb = 0, *c1 = 0, *c2 = 0, *c3 = 0;
    for (int i = 0; i < n_in; ++i) {
        const float* p = (const float*)d_in[i];
        switch (in_sizes[i]) {
            case 8388608: X  = p; break;
            case 144:     cw = p; break;
            case 16:      cb = p; break;
            case 4096:    c1 = p; break;
            case 16384:   c2 = p; break;
            case 1024:    c3 = p; break;
            default: break;
        }
    }

    cudaFuncSetAttribute(conv_mma, cudaFuncAttributeMaxDynamicSharedMemorySize,
                         SMEM_DYN);

    precompute_P<<<256, 256>>>(c2, c3);
    precompute_W<<<4096, 256>>>(c1);
    precompute_Weff<<<256, 256>>>(cw, cb);
    zero_borders<<<260, 256>>>();
    build_xpad<<<dim3(64, 8, 8), 256>>>(X);

    conv_mma<<<dim3(16, 8, 2), 512, SMEM_DYN>>>((float*)d_out);
}

// round 5
// speedup vs baseline: 7.4506x; 1.0142x over previous
#include <cuda_runtime.h>
#include <cuda_fp16.h>
#include <cstdint>

// ============================================================================
// TTConv folded into ONE dense 256->256 3x3 conv, executed as fp16 mma.sync
// implicit GEMM. Precompute collapsed to 2 kernels via tap-folding into G1:
//   P[c,d,j,k,u]    = sum_v G2[c,v,u,j] * G3[d,v,k]
//   G1f[a,i,tap,u]  = sum_r G1[a,u,r,i] * conv_w[r,tap]
//   g1b[a,i,u]      = sum_r G1[a,u,r,i] * conv_b[r]
//   Weff[o,ic,tap]  = sum_u G1f[a,i,tap,u] * P[c,d,j,k,u]   (direct, no g_W)
//   beff[o]         = sum_ic sum_u g1b[a,i,u] * P[c,d,j,k,u]
// ============================================================================

// ---------------- device scratch (no allocations allowed) -------------------
__device__ float  g_P[8 * 8 * 8 * 8 * 16];
__device__ float  g_G1f[4 * 4 * 9 * 16];            // [a][i][tap][u]
__device__ float  g_g1b[4 * 4 * 16];                // [a][i][u]
// A, pre-swizzled: [Mhalf 2][icb 8][tap 9][o_local 128][k 32(swizzled)]
__device__ __half g_Wsw[2 * 8 * 9 * 128 * 32];
__device__ float  g_beff[256];
__device__ __half g_Xh[8ull * 66 * 66 * 256];       // padded NHWC fp16

// ---------------- helpers ---------------------------------------------------
__device__ __forceinline__ uint32_t smem_u32(const void* p) {
    uint32_t a;
    asm("{ .reg .u64 t; cvta.to.shared.u64 t, %1; cvt.u32.u64 %0, t; }"
        : "=r"(a) : "l"(p));
    return a;
}

#define CP16(dst, src) \
    asm volatile("cp.async.ca.shared.global [%0], [%1], 16;" \
                 :: "r"(dst), "l"(src) : "memory")
#define CP_COMMIT() asm volatile("cp.async.commit_group;" ::: "memory")
#define CP_WAIT1()  asm volatile("cp.async.wait_group 1;" ::: "memory")
#define CP_WAIT0()  asm volatile("cp.async.wait_group 0;" ::: "memory")

#define LDSM4(r0, r1, r2, r3, addr) \
    asm volatile("ldmatrix.sync.aligned.m8n8.x4.shared.b16 {%0,%1,%2,%3}, [%4];" \
                 : "=r"(r0), "=r"(r1), "=r"(r2), "=r"(r3) : "r"(addr))

#define MMA16816(c, a0, a1, a2, a3, b0, b1) \
    asm volatile("mma.sync.aligned.m16n8k16.row.col.f32.f16.f16.f32 " \
                 "{%0,%1,%2,%3}, {%4,%5,%6,%7}, {%8,%9}, {%0,%1,%2,%3};" \
                 : "+f"((c)[0]), "+f"((c)[1]), "+f"((c)[2]), "+f"((c)[3]) \
                 : "r"(a0), "r"(a1), "r"(a2), "r"(a3), "r"(b0), "r"(b1))

// ---------------------------------------------------------------------------
// K1: P (blocks 0..255) + G1f/g1b (block 256)
// ---------------------------------------------------------------------------
__global__ void precompute_PG(const float* __restrict__ core1,
                              const float* __restrict__ core2,
                              const float* __restrict__ core3,
                              const float* __restrict__ conv_w,
                              const float* __restrict__ conv_b) {
    if (blockIdx.x < 256) {
        int idx = blockIdx.x * 256 + threadIdx.x;
        int u = idx & 15, k = (idx >> 4) & 7, j = (idx >> 7) & 7;
        int d = (idx >> 10) & 7, c = idx >> 13;
        float s = 0.f;
#pragma unroll
        for (int v = 0; v < 16; ++v)
            s += core2[(c * 16 + v) * 128 + u * 8 + j] * core3[d * 128 + v * 8 + k];
        g_P[idx] = s;
    } else {
        // G1f: 2304 elems ([a][i][tap][u]); g1b: 256 elems ([a][i][u])
        int t = threadIdx.x;
        for (int e = t; e < 2304; e += 256) {
            int u = e & 15, tap = (e >> 4) % 9, ai = e / 144;
            int a = ai >> 2, i = ai & 3;
            float s = 0.f;
#pragma unroll
            for (int r = 0; r < 16; ++r)
                s += core1[(a * 16 + u) * 64 + r * 4 + i] * conv_w[r * 9 + tap];
            g_G1f[e] = s;
        }
        if (t < 256) {
            int u = t & 15, ai = t >> 4;
            int a = ai >> 2, i = ai & 3;
            float s = 0.f;
#pragma unroll
            for (int r = 0; r < 16; ++r)
                s += core1[(a * 16 + u) * 64 + r * 4 + i] * conv_b[r];
            g_g1b[t] = s;
        }
    }
}

// ---------------------------------------------------------------------------
// K2: Weff (swizzled fp16 A) + beff, directly from P and G1f/g1b.
//   grid 256 (o), block 256 (ic)
// ---------------------------------------------------------------------------
__global__ void precompute_Weff(int dummy) {
    int o = blockIdx.x, ic = threadIdx.x;
    int a = o >> 6, c = (o >> 3) & 7, d = o & 7;
    int i = ic >> 6, j = (ic >> 3) & 7, k = ic & 7;
    float Pu[16];
    const float* Pp = &g_P[(((c * 8 + d) * 8 + j) * 8 + k) * 16];
#pragma unroll
    for (int u = 0; u < 16; ++u) Pu[u] = Pp[u];

    int kk = ic & 31, icb = ic >> 5;
    int o_l = o & 127, mh = o >> 7;
    int swkk = ((((kk >> 3) ^ ((o_l >> 1) & 3)) << 3) | (kk & 7));
    const float* G1fp = &g_G1f[(a * 4 + i) * 144];
#pragma unroll
    for (int tap = 0; tap < 9; ++tap) {
        float s = 0.f;
#pragma unroll
        for (int u = 0; u < 16; ++u) s += G1fp[tap * 16 + u] * Pu[u];
        g_Wsw[((((size_t)mh * 8 + icb) * 9 + tap) * 128 + o_l) * 32 + swkk] =
            __float2half_rn(s);
    }
    const float* g1bp = &g_g1b[(a * 4 + i) * 16];
    float bp = 0.f;
#pragma unroll
    for (int u = 0; u < 16; ++u) bp += g1bp[u] * Pu[u];
    __shared__ float red[256];
    red[ic] = bp;
    __syncthreads();
    for (int s = 128; s > 0; s >>= 1) {
        if (ic < s) red[ic] += red[ic + s];
        __syncthreads();
    }
    if (ic == 0) g_beff[o] = red[0];
}

// ---------------------------------------------------------------------------
// K3: NCHW fp32 -> padded NHWC fp16 interior (x<64) + border zeroing (x==64)
// ---------------------------------------------------------------------------
__global__ void build_xpad(const float* __restrict__ X) {
    int y = blockIdx.x, icb = blockIdx.y, b = blockIdx.z;
    int tid = threadIdx.x;
    if (y == 64) {
        // zero borders for this (b, icb) slice: 260 pixels x 4 uint4
        for (int e = tid; e < 1040; e += 256) {
            int p = e >> 2, q = e & 3;
            int yy, xx;
            if (p < 66)        { yy = 0;       xx = p; }
            else if (p < 132)  { yy = 65;      xx = p - 66; }
            else if (p < 196)  { yy = p - 131; xx = 0; }
            else               { yy = p - 195; xx = 65; }
            reinterpret_cast<uint4*>(
                g_Xh + (((size_t)b * 66 + yy) * 66 + xx) * 256 + icb * 32)[q] =
                make_uint4(0, 0, 0, 0);
        }
        return;
    }
    __shared__ float s[32 * 65];
    for (int i = tid; i < 2048; i += 256) {
        int icl = i >> 6, x = i & 63;
        s[icl * 65 + x] = X[(((size_t)b * 256 + icb * 32 + icl) * 64 + y) * 64 + x];
    }
    __syncthreads();
    for (int i = tid; i < 1024; i += 256) {
        int x = i >> 4, pr = i & 15;
        __half2 h = __floats2half2_rn(s[(2 * pr) * 65 + x], s[(2 * pr + 1) * 65 + x]);
        *reinterpret_cast<__half2*>(
            g_Xh + (((size_t)b * 66 + y + 1) * 66 + (x + 1)) * 256 + icb * 32 + 2 * pr) = h;
    }
}

// ---------------------------------------------------------------------------
// Main kernel (unchanged structure). CTA: 128 o x 256 pixels. 512 thr.
// ---------------------------------------------------------------------------
static constexpr int A_CH   = 8192;
static constexpr int A_BUF  = 9 * A_CH;        // 73728
static constexpr int XS_BUF = 31680;           // 396 rows x 80B
static constexpr int XS_OFF = 2 * A_BUF;       // 147456
static constexpr int SMEM_DYN = XS_OFF + 2 * XS_BUF;  // 210816

__global__ __launch_bounds__(512, 1)
void conv_mma(float* __restrict__ out) {
    extern __shared__ char smc[];
    const uint32_t sb = smem_u32(smc);
    const int tid  = threadIdx.x;
    const int warp = tid >> 5, lane = tid & 31;
    const int warpM = warp >> 2;
    const int warpR = warp & 3;
    const int h0 = blockIdx.x * 4;
    const int b  = blockIdx.y;
    const int Mbase = blockIdx.z * 128;
    const int mh = blockIdx.z;

    const int rowA = warpM * 32 + (lane & 15);
    const int hi   = lane >> 4;
    const int swA  = ((lane & 15) >> 1) & 3;
    const uint32_t aLane0 = (uint32_t)(rowA * 64 + ((hi ^ swA) << 4));
    const uint32_t aLane1 = (uint32_t)(rowA * 64 + (((2 + hi) ^ swA) << 4));
    const uint32_t xLane = (uint32_t)((((lane >> 4) & 1) * 8 + (lane & 7)) * 80 +
                                      ((lane >> 3) & 1) * 16);

    auto stageA = [&](int icb, int buf) {
        const char* src = (const char*)(g_Wsw + (((size_t)mh * 8 + icb) * 9) * 128 * 32);
        uint32_t dst = sb + buf * A_BUF;
#pragma unroll
        for (int i = 0; i < 9; ++i) {
            int e = tid + i * 512;
            CP16(dst + e * 16, src + e * 16);
        }
    };
    auto stageXs = [&](int icb, int buf) {
        uint32_t dst = sb + XS_OFF + buf * XS_BUF;
        const char* base = (const char*)g_Xh;
        for (int e = tid; e < 1584; e += 512) {
            int pix = e >> 2, c = e & 3;
            int yy = pix / 66, cc = pix - yy * 66;
            const char* src = base +
                ((((size_t)b * 66 + h0 + yy) * 66 + cc) * 256 + icb * 32) * 2 + c * 16;
            CP16(dst + pix * 80 + c * 16, src);
        }
    };

    float acc[2][8][4];
#pragma unroll
    for (int m = 0; m < 2; ++m)
#pragma unroll
        for (int n = 0; n < 8; ++n)
#pragma unroll
            for (int q = 0; q < 4; ++q) acc[m][n][q] = 0.f;

    stageXs(0, 0); stageA(0, 0); CP_COMMIT();
    stageXs(1, 1); stageA(1, 1); CP_COMMIT();

    for (int icb = 0; icb < 8; ++icb) {
        const int buf = icb & 1;
        if (icb < 7) CP_WAIT1(); else CP_WAIT0();
        __syncthreads();

        const uint32_t aBase = sb + buf * A_BUF;
        const uint32_t xBase = sb + XS_OFF + buf * XS_BUF;

#pragma unroll
        for (int tap = 0; tap < 9; ++tap) {
            const int dy = tap / 3, dx = tap - dy * 3;
            const uint32_t aT = aBase + tap * A_CH;
            const uint32_t xT = xBase + (uint32_t)(((warpR + dy) * 66 + dx) * 80) + xLane;

#pragma unroll
            for (int ks = 0; ks < 2; ++ks) {
                const uint32_t aAddr = aT + (ks ? aLane1 : aLane0);
                uint32_t a0, a1, a2, a3, e0, e1, e2, e3;
                LDSM4(a0, a1, a2, a3, aAddr);
                LDSM4(e0, e1, e2, e3, aAddr + 16 * 64);
#pragma unroll
                for (int p = 0; p < 4; ++p) {
                    uint32_t b0, b1, b2, b3;
                    LDSM4(b0, b1, b2, b3, xT + p * (16 * 80) + ks * 32);
                    MMA16816(acc[0][2 * p],     a0, a1, a2, a3, b0, b1);
                    MMA16816(acc[0][2 * p + 1], a0, a1, a2, a3, b2, b3);
                    MMA16816(acc[1][2 * p],     e0, e1, e2, e3, b0, b1);
                    MMA16816(acc[1][2 * p + 1], e0, e1, e2, e3, b2, b3);
                }
            }
        }
        __syncthreads();
        if (icb + 2 < 8) {
            stageXs(icb + 2, buf);
            stageA(icb + 2, buf);
            CP_COMMIT();
        }
    }

    const int h = h0 + warpR;
#pragma unroll
    for (int mt = 0; mt < 2; ++mt) {
        int oLo = Mbase + warpM * 32 + mt * 16 + (lane >> 2);
        float bvLo = g_beff[oLo];
        float bvHi = g_beff[oLo + 8];
        float* rowLo = out + (((size_t)b * 256 + oLo) * 64 + h) * 64;
        float* rowHi = rowLo + (size_t)8 * 64 * 64;
#pragma unroll
        for (int nt = 0; nt < 8; ++nt) {
            int w = nt * 8 + (lane & 3) * 2;
            float2 vLo = make_float2(acc[mt][nt][0] + bvLo, acc[mt][nt][1] + bvLo);
            float2 vHi = make_float2(acc[mt][nt][2] + bvHi, acc[mt][nt][3] + bvHi);
            *reinterpret_cast<float2*>(rowLo + w) = vLo;
            *reinterpret_cast<float2*>(rowHi + w) = vHi;
        }
    }
}

// ---------------------------------------------------------------------------
extern "C" void kernel_launch(void* const* d_in, const int* in_sizes, int n_in,
                              void* d_out, int out_size) {
    const float *X = 0, *cw = 0, *cb = 0, *c1 = 0, *c2 = 0, *c3 = 0;
    for (int i = 0; i < n_in; ++i) {
        const float* p = (const float*)d_in[i];
        switch (in_sizes[i]) {
            case 8388608: X  = p; break;
            case 144:     cw = p; break;
            case 16:      cb = p; break;
            case 4096:    c1 = p; break;
            case 16384:   c2 = p; break;
            case 1024:    c3 = p; break;
            default: break;
        }
    }

    cudaFuncSetAttribute(conv_mma, cudaFuncAttributeMaxDynamicSharedMemorySize,
                         SMEM_DYN);

    precompute_PG<<<257, 256>>>(c1, c2, c3, cw, cb);
    precompute_Weff<<<256, 256>>>(0);
    build_xpad<<<dim3(65, 8, 8), 256>>>(X);

    conv_mma<<<dim3(16, 8, 2), 512, SMEM_DYN>>>((float*)d_out);
}